// round 14
// baseline (speedup 1.0000x reference)
#include <cuda_runtime.h>
#include <cuda_bf16.h>
#include <math.h>
#include <stdint.h>

#define NMAX 50176
#define EMAX 800000
#define TILES_MAX 392
#define PITCH 136

typedef unsigned long long u64;

// ---- device scratch (no runtime allocation allowed) ----
__device__ float  g_xl[NMAX * 128];
__device__ float  g_xr[NMAX * 128];
__device__ int    g_counts[NMAX];
__device__ int    g_partial[64];
__device__ int    g_pflag[64];
__device__ int    g_rowptr[NMAX + 1];
__device__ int    g_cursor[NMAX];
__device__ int    g_csrc  [EMAX];
__device__ int    g_wcnt[2];          // dynamic work counters (agg1, agg2)
// layer-2 input as split-bf16 in GEMM smem-mirror layout (pitch 136 per 128-row tile)
__device__ unsigned short g_Ah[TILES_MAX * 128 * PITCH];
__device__ unsigned short g_Al[TILES_MAX * 128 * PITCH];
// precomputed W^T split-bf16, packed [n][k]; slots: W1l,W1r,W2l,W2r
__device__ unsigned short g_Bh[4 * 16384];
__device__ unsigned short g_Bl[4 * 16384];

// ---------------- CSR build ----------------
__global__ void k_hist(const int* __restrict__ ei, int E) {
    int t = blockIdx.x * blockDim.x + threadIdx.x;
    int e = t << 2;
    if (e + 3 < E && (E & 3) == 0) {
        int4 d = *(const int4*)(ei + E + e);
        atomicAdd(&g_counts[d.x], 1);
        atomicAdd(&g_counts[d.y], 1);
        atomicAdd(&g_counts[d.z], 1);
        atomicAdd(&g_counts[d.w], 1);
    } else {
        for (int k = e; k < min(e + 4, E); k++)
            atomicAdd(&g_counts[ei[E + k]], 1);
    }
}

// single-kernel scan: warp-shuffle block scan + parallel lookback
__global__ __launch_bounds__(1024) void k_scan_one(int n) {
    __shared__ int wsum[32];
    __shared__ int sh_off;
    int tid = threadIdx.x, b = blockIdx.x;
    int lane = tid & 31, wid = tid >> 5;
    int i = b * 1024 + tid;
    int v = (i < n) ? g_counts[i] : 0;
    int s = v;
#pragma unroll
    for (int o = 1; o < 32; o <<= 1) {
        int t = __shfl_up_sync(0xffffffffu, s, o);
        if (lane >= o) s += t;
    }
    if (lane == 31) wsum[wid] = s;
    __syncthreads();
    if (wid == 0) {
        int ss = wsum[lane];
#pragma unroll
        for (int o = 1; o < 32; o <<= 1) {
            int t = __shfl_up_sync(0xffffffffu, ss, o);
            if (lane >= o) ss += t;
        }
        wsum[lane] = ss;
    }
    __syncthreads();
    int incl = s + (wid ? wsum[wid - 1] : 0);
    if (tid == 1023) {
        g_partial[b] = incl;
        __threadfence();
        atomicExch(&g_pflag[b], 1);
    }
    if (tid < 32) {
        int off = 0;
        for (int j = tid; j < b; j += 32) {
            while (atomicAdd(&g_pflag[j], 0) == 0) { }
            off += atomicAdd(&g_partial[j], 0);
        }
#pragma unroll
        for (int st = 16; st; st >>= 1) off += __shfl_xor_sync(0xffffffffu, off, st);
        if (tid == 0) sh_off = off;
    }
    __syncthreads();
    if (i < n) {
        int gincl = sh_off + incl;
        int excl = gincl - v;
        g_rowptr[i] = excl;
        g_cursor[i] = excl;
        if (i == n - 1) g_rowptr[n] = gincl;
    }
}

__global__ void k_scatter(const int* __restrict__ ei, int E) {
    int t = blockIdx.x * blockDim.x + threadIdx.x;
    int e = t << 2;
    if (e + 3 < E && (E & 3) == 0) {
        int4 s = *(const int4*)(ei + e);
        int4 d = *(const int4*)(ei + E + e);
        g_csrc[atomicAdd(&g_cursor[d.x], 1)] = s.x;
        g_csrc[atomicAdd(&g_cursor[d.y], 1)] = s.y;
        g_csrc[atomicAdd(&g_cursor[d.z], 1)] = s.z;
        g_csrc[atomicAdd(&g_cursor[d.w], 1)] = s.w;
    } else {
        for (int k = e; k < min(e + 4, E); k++)
            g_csrc[atomicAdd(&g_cursor[ei[E + k]], 1)] = ei[k];
    }
}

// ---- split-bf16 helpers ----
__device__ __forceinline__ unsigned short bf_hi(float f) {
    return __bfloat16_as_ushort(__float2bfloat16(f));
}
__device__ __forceinline__ unsigned short bf_lo(float f, unsigned short hi) {
    float fh = __bfloat162float(__ushort_as_bfloat16(hi));
    return __bfloat16_as_ushort(__float2bfloat16(f - fh));
}

// ---------------- one-shot W conversion (also resets work counters) ----------
__global__ void k_cvtW_all(const float* __restrict__ W0, const float* __restrict__ W1,
                           const float* __restrict__ W2, const float* __restrict__ W3) {
    int idx = blockIdx.x * blockDim.x + threadIdx.x;
    if (idx == 0) { g_wcnt[0] = 0; g_wcnt[1] = 0; }
    int slot = idx >> 14;
    int rem = idx & 16383;
    int k = rem >> 7;
    int n = rem & 127;
    const float* W = (slot == 0) ? W0 : (slot == 1) ? W1 : (slot == 2) ? W2 : W3;
    float w = W[rem];
    unsigned short h = bf_hi(w);
    int off = (slot << 14) + (n << 7) + k;
    g_Bh[off] = h;
    g_Bl[off] = bf_lo(w, h);
}

// =================== split-bf16 HMMA GEMM ===================
#define AS_H 0
#define AS_L (128 * PITCH)
#define BS_H (2 * 128 * PITCH)
#define BS_L (3 * 128 * PITCH)
#define GEMM_SMEM_BYTES (4 * 128 * PITCH * 2)
#define A_TILE_U4 2176

__device__ __forceinline__ uint32_t smem_u32(const void* p) {
    uint32_t a;
    asm("{ .reg .u64 t; cvta.to.shared.u64 t, %1; cvt.u32.u64 %0, t; }"
        : "=r"(a) : "l"(p));
    return a;
}

__device__ __forceinline__ void ldsm4(uint32_t& r0, uint32_t& r1, uint32_t& r2,
                                      uint32_t& r3, uint32_t addr) {
    asm volatile("ldmatrix.sync.aligned.m8n8.x4.shared.b16 {%0,%1,%2,%3}, [%4];"
        : "=r"(r0), "=r"(r1), "=r"(r2), "=r"(r3) : "r"(addr));
}

__device__ __forceinline__ void mma16816(float* c, uint32_t a0, uint32_t a1,
                                         uint32_t a2, uint32_t a3,
                                         uint32_t b0, uint32_t b1) {
    asm volatile(
        "mma.sync.aligned.m16n8k16.row.col.f32.bf16.bf16.f32 "
        "{%0,%1,%2,%3}, {%4,%5,%6,%7}, {%8,%9}, {%0,%1,%2,%3};"
        : "+f"(c[0]), "+f"(c[1]), "+f"(c[2]), "+f"(c[3])
        : "r"(a0), "r"(a1), "r"(a2), "r"(a3), "r"(b0), "r"(b1));
}

// ACOPY=false: A converted in-kernel from fp32. ACOPY=true: A copied from g_Ah/g_Al.
template<bool ACOPY>
__global__ __launch_bounds__(256, 1) void k_gemm_mma(
    const float* __restrict__ A,
    const float* __restrict__ bl, float* __restrict__ Cl,
    const float* __restrict__ br, float* __restrict__ Cr,
    int slot0, int M)
{
    extern __shared__ __align__(16) unsigned short sm[];
    int sel = blockIdx.y;
    const float* bias = sel ? br : bl;
    float* C = sel ? Cr : Cl;
    int slot = slot0 + sel;

    int tid = threadIdx.x;
    int row0 = blockIdx.x << 7;

    if (ACOPY) {
        const uint4* sAh = (const uint4*)(g_Ah + (size_t)blockIdx.x * 128 * PITCH);
        const uint4* sAl = (const uint4*)(g_Al + (size_t)blockIdx.x * 128 * PITCH);
        uint4* dAh = (uint4*)(sm + AS_H);
        uint4* dAl = (uint4*)(sm + AS_L);
#pragma unroll
        for (int i = 0; i < 9; i++) {
            int p = tid + (i << 8);
            if (p < A_TILE_U4) {
                dAh[p] = sAh[p];
                dAl[p] = sAl[p];
            }
        }
    } else {
        const float4* A4 = (const float4*)(A + (size_t)row0 * 128);
#pragma unroll
        for (int i = 0; i < 16; i++) {
            int idx = tid + (i << 8);
            int r = idx >> 5;
            int c = (idx & 31) << 2;
            float4 v = (row0 + r < M) ? A4[idx] : make_float4(0.f, 0.f, 0.f, 0.f);
            ushort4 h, l;
            h.x = bf_hi(v.x); l.x = bf_lo(v.x, h.x);
            h.y = bf_hi(v.y); l.y = bf_lo(v.y, h.y);
            h.z = bf_hi(v.z); l.z = bf_lo(v.z, h.z);
            h.w = bf_hi(v.w); l.w = bf_lo(v.w, h.w);
            *(ushort4*)&sm[AS_H + r * PITCH + c] = h;
            *(ushort4*)&sm[AS_L + r * PITCH + c] = l;
        }
    }
    {
        const uint4* srcH = (const uint4*)(g_Bh + ((size_t)slot << 14));
        const uint4* srcL = (const uint4*)(g_Bl + ((size_t)slot << 14));
#pragma unroll
        for (int i = 0; i < 8; i++) {
            int v = tid + (i << 8);
            int e = v << 3;
            int n = e >> 7, k = e & 127;
            int d = n * PITCH + k;
            *(uint4*)&sm[BS_H + d] = srcH[v];
            *(uint4*)&sm[BS_L + d] = srcL[v];
        }
    }
    __syncthreads();

    int wid = tid >> 5, lane = tid & 31;
    int wm = (wid >> 1) << 5;
    int wn = (wid & 1) << 6;

    float acc[2][8][4];
#pragma unroll
    for (int mt = 0; mt < 2; mt++)
#pragma unroll
        for (int nt = 0; nt < 8; nt++)
#pragma unroll
            for (int q = 0; q < 4; q++) acc[mt][nt][q] = 0.f;

    int a_row = lane & 15;
    int a_col = (lane >> 4) << 3;
    int b_row = ((lane >> 4) << 3) + (lane & 7);
    int b_col = ((lane >> 3) & 1) << 3;

    uint32_t sb = smem_u32(sm);
    const int APASS[3] = {AS_H, AS_H, AS_L};
    const int BPASS[3] = {BS_H, BS_L, BS_H};

#pragma unroll
    for (int pass = 0; pass < 3; pass++) {
        uint32_t abase = sb + ((uint32_t)(APASS[pass] + (wm + a_row) * PITCH + a_col) << 1);
        uint32_t bbase = sb + ((uint32_t)(BPASS[pass] + (wn + b_row) * PITCH + b_col) << 1);
#pragma unroll
        for (int ks = 0; ks < 8; ks++) {
            int k0 = ks << 4;
            uint32_t af[2][4];
            ldsm4(af[0][0], af[0][1], af[0][2], af[0][3], abase + (k0 << 1));
            ldsm4(af[1][0], af[1][1], af[1][2], af[1][3],
                  abase + (k0 << 1) + (16 * PITCH << 1));
            uint32_t bf[4][4];
#pragma unroll
            for (int g = 0; g < 4; g++)
                ldsm4(bf[g][0], bf[g][1], bf[g][2], bf[g][3],
                      bbase + (k0 << 1) + ((g * 16 * PITCH) << 1));
#pragma unroll
            for (int mt = 0; mt < 2; mt++)
#pragma unroll
                for (int nt = 0; nt < 8; nt++) {
                    uint32_t b0 = bf[nt >> 1][(nt & 1) << 1];
                    uint32_t b1 = bf[nt >> 1][((nt & 1) << 1) + 1];
                    mma16816(acc[mt][nt], af[mt][0], af[mt][1], af[mt][2], af[mt][3], b0, b1);
                }
        }
    }

    int g = lane >> 2, tg = lane & 3;
#pragma unroll
    for (int mt = 0; mt < 2; mt++) {
        int rlo = row0 + wm + (mt << 4) + g;
        int rhi = rlo + 8;
#pragma unroll
        for (int nt = 0; nt < 8; nt++) {
            int col = wn + (nt << 3) + (tg << 1);
            float2 bv = *(const float2*)(bias + col);
            if (rlo < M)
                *(float2*)(C + (size_t)rlo * 128 + col) =
                    make_float2(acc[mt][nt][0] + bv.x, acc[mt][nt][1] + bv.y);
            if (rhi < M)
                *(float2*)(C + (size_t)rhi * 128 + col) =
                    make_float2(acc[mt][nt][2] + bv.x, acc[mt][nt][3] + bv.y);
        }
    }
}

// ---------------- GATv2 aggregation: dynamic warp work assignment --------------
// Warps grab nodes from a global counter (next-grab pipelined over current node).
// Per-node body identical to the proven R10 kernel (fp32 gathers, 4-edge batches).
template<bool FULLWARP, bool DOELU, bool SPLITOUT>
__global__ __launch_bounds__(256) void k_agg(
    const float* __restrict__ xl, const float* __restrict__ xr,
    const float* __restrict__ att, const float* __restrict__ bias,
    float* __restrict__ out, unsigned short* __restrict__ oh,
    unsigned short* __restrict__ ol, int n, int cidx)
{
    int lane = threadIdx.x & 31;
    const float LOG2E = 1.4426950408889634f;

    float4 attv = *(const float4*)(att + (lane << 2));
    attv.x *= LOG2E; attv.y *= LOG2E; attv.z *= LOG2E; attv.w *= LOG2E;

    const float4* xlp = (const float4*)xl;

    int node = 0;
    if (lane == 0) node = atomicAdd(&g_wcnt[cidx], 1);
    node = __shfl_sync(0xffffffffu, node, 0);

    while (node < n) {
        // pipeline next grab over this node's work
        int nxt = 0;
        if (lane == 0) nxt = atomicAdd(&g_wcnt[cidx], 1);
        nxt = __shfl_sync(0xffffffffu, nxt, 0);

        float4 xrv = *(const float4*)(xr + (size_t)node * 128 + (lane << 2));
        int beg = g_rowptr[node];
        int cnt = g_rowptr[node + 1] - beg;

        float denom = 0.f;
        float4 acc = make_float4(0.f, 0.f, 0.f, 0.f);

#define EDGE_PART(v, part)                                                     \
    {                                                                          \
        float tx = (v).x + xrv.x; tx = fmaxf(tx, 0.2f * tx);                   \
        float ty = (v).y + xrv.y; ty = fmaxf(ty, 0.2f * ty);                   \
        float tz = (v).z + xrv.z; tz = fmaxf(tz, 0.2f * tz);                   \
        float tw = (v).w + xrv.w; tw = fmaxf(tw, 0.2f * tw);                   \
        part = attv.x * tx;                                                    \
        part = fmaf(attv.y, ty, part);                                         \
        part = fmaf(attv.z, tz, part);                                         \
        part = fmaf(attv.w, tw, part);                                         \
    }
#define REDUCE_PART(part)                                                      \
    part += __shfl_xor_sync(0xffffffffu, part, 1);                             \
    part += __shfl_xor_sync(0xffffffffu, part, 2);                             \
    part += __shfl_xor_sync(0xffffffffu, part, 4);                             \
    if (FULLWARP) {                                                            \
        part += __shfl_xor_sync(0xffffffffu, part, 8);                         \
        part += __shfl_xor_sync(0xffffffffu, part, 16);                        \
    }

        // self-loop first
        {
            float4 v = xlp[(size_t)node * 32 + lane];
            float part;
            EDGE_PART(v, part);
            REDUCE_PART(part);
            float p;
            asm("ex2.approx.f32 %0, %1;" : "=f"(p) : "f"(part));
            denom += p;
            acc.x = fmaf(p, v.x, acc.x);
            acc.y = fmaf(p, v.y, acc.y);
            acc.z = fmaf(p, v.z, acc.z);
            acc.w = fmaf(p, v.w, acc.w);
        }

        float4 c0, c1, c2, c3;
        {
            int i0 = (0 < cnt) ? g_csrc[beg + 0] : node;
            int i1 = (1 < cnt) ? g_csrc[beg + 1] : node;
            int i2 = (2 < cnt) ? g_csrc[beg + 2] : node;
            int i3 = (3 < cnt) ? g_csrc[beg + 3] : node;
            c0 = xlp[(size_t)i0 * 32 + lane];
            c1 = xlp[(size_t)i1 * 32 + lane];
            c2 = xlp[(size_t)i2 * 32 + lane];
            c3 = xlp[(size_t)i3 * 32 + lane];
        }

        for (int j = 0; j < cnt; j += 4) {
            float4 n0 = c0, n1 = c1, n2 = c2, n3 = c3;
            int jn = j + 4;
            if (jn < cnt) {
                int i0 = (jn + 0 < cnt) ? g_csrc[beg + jn + 0] : node;
                int i1 = (jn + 1 < cnt) ? g_csrc[beg + jn + 1] : node;
                int i2 = (jn + 2 < cnt) ? g_csrc[beg + jn + 2] : node;
                int i3 = (jn + 3 < cnt) ? g_csrc[beg + jn + 3] : node;
                n0 = xlp[(size_t)i0 * 32 + lane];
                n1 = xlp[(size_t)i1 * 32 + lane];
                n2 = xlp[(size_t)i2 * 32 + lane];
                n3 = xlp[(size_t)i3 * 32 + lane];
            }

            float p0, p1, p2, p3;
            EDGE_PART(c0, p0);
            EDGE_PART(c1, p1);
            EDGE_PART(c2, p2);
            EDGE_PART(c3, p3);
            REDUCE_PART(p0);
            REDUCE_PART(p1);
            REDUCE_PART(p2);
            REDUCE_PART(p3);
            float e0, e1, e2, e3;
            asm("ex2.approx.f32 %0, %1;" : "=f"(e0) : "f"(p0));
            asm("ex2.approx.f32 %0, %1;" : "=f"(e1) : "f"(p1));
            asm("ex2.approx.f32 %0, %1;" : "=f"(e2) : "f"(p2));
            asm("ex2.approx.f32 %0, %1;" : "=f"(e3) : "f"(p3));
            e0 = (j + 0 < cnt) ? e0 : 0.f;
            e1 = (j + 1 < cnt) ? e1 : 0.f;
            e2 = (j + 2 < cnt) ? e2 : 0.f;
            e3 = (j + 3 < cnt) ? e3 : 0.f;

            denom += (e0 + e1) + (e2 + e3);
            acc.x = fmaf(e0, c0.x, fmaf(e1, c1.x, fmaf(e2, c2.x, fmaf(e3, c3.x, acc.x))));
            acc.y = fmaf(e0, c0.y, fmaf(e1, c1.y, fmaf(e2, c2.y, fmaf(e3, c3.y, acc.y))));
            acc.z = fmaf(e0, c0.z, fmaf(e1, c1.z, fmaf(e2, c2.z, fmaf(e3, c3.z, acc.z))));
            acc.w = fmaf(e0, c0.w, fmaf(e1, c1.w, fmaf(e2, c2.w, fmaf(e3, c3.w, acc.w))));

            c0 = n0; c1 = n1; c2 = n2; c3 = n3;
        }
#undef EDGE_PART
#undef REDUCE_PART

        float inv = 1.f / denom;
        float4 bv = *(const float4*)(bias + (lane << 2));
        float ox = fmaf(acc.x, inv, bv.x);
        float oy = fmaf(acc.y, inv, bv.y);
        float oz = fmaf(acc.z, inv, bv.z);
        float ow = fmaf(acc.w, inv, bv.w);
        if (DOELU) {
            ox = ox > 0.f ? ox : __expf(ox) - 1.f;
            oy = oy > 0.f ? oy : __expf(oy) - 1.f;
            oz = oz > 0.f ? oz : __expf(oz) - 1.f;
            ow = ow > 0.f ? ow : __expf(ow) - 1.f;
        }
        if (SPLITOUT) {
            int tile = node >> 7, r = node & 127;
            size_t off = (size_t)tile * 128 * PITCH + r * PITCH + (lane << 2);
            ushort4 hh, ll;
            hh.x = bf_hi(ox); ll.x = bf_lo(ox, hh.x);
            hh.y = bf_hi(oy); ll.y = bf_lo(oy, hh.y);
            hh.z = bf_hi(oz); ll.z = bf_lo(oz, hh.z);
            hh.w = bf_hi(ow); ll.w = bf_lo(ow, hh.w);
            *(ushort4*)&oh[off] = hh;
            *(ushort4*)&ol[off] = ll;
        } else {
            *(float4*)(out + (size_t)node * 128 + (lane << 2)) =
                make_float4(ox, oy, oz, ow);
        }

        node = nxt;
    }
}

// ---------------- host launcher ----------------
extern "C" void kernel_launch(void* const* d_in, const int* in_sizes, int n_in,
                              void* d_out, int out_size)
{
    const float* x     = (const float*)d_in[0];
    const int*   ei    = (const int*)  d_in[1];
    const float* W1l   = (const float*)d_in[2];
    const float* b1l   = (const float*)d_in[3];
    const float* W1r   = (const float*)d_in[4];
    const float* b1r   = (const float*)d_in[5];
    const float* att1  = (const float*)d_in[6];
    const float* bias1 = (const float*)d_in[7];
    const float* W2l   = (const float*)d_in[8];
    const float* b2l   = (const float*)d_in[9];
    const float* W2r   = (const float*)d_in[10];
    const float* b2r   = (const float*)d_in[11];
    const float* att2  = (const float*)d_in[12];
    const float* bias2 = (const float*)d_in[13];

    int N = in_sizes[0] / 128;
    int E = in_sizes[1] / 2;
    int tiles = (N + 127) / 128;
    int sblocks = (N + 1023) / 1024;

    void *p_xl, *p_xr, *p_Ah, *p_Al, *p_counts, *p_pflag;
    cudaGetSymbolAddress(&p_xl, g_xl);
    cudaGetSymbolAddress(&p_xr, g_xr);
    cudaGetSymbolAddress(&p_Ah, g_Ah);
    cudaGetSymbolAddress(&p_Al, g_Al);
    cudaGetSymbolAddress(&p_counts, g_counts);
    cudaGetSymbolAddress(&p_pflag, g_pflag);
    float* xl = (float*)p_xl;
    float* xr = (float*)p_xr;
    unsigned short* Ahp = (unsigned short*)p_Ah;
    unsigned short* Alp = (unsigned short*)p_Al;

    static cudaStream_t s_csr = nullptr;
    static cudaEvent_t ev_fork = nullptr, ev_join = nullptr;
    static bool s_attr = false;
    if (s_csr == nullptr) {
        cudaStreamCreateWithFlags(&s_csr, cudaStreamNonBlocking);
        cudaEventCreateWithFlags(&ev_fork, cudaEventDisableTiming);
        cudaEventCreateWithFlags(&ev_join, cudaEventDisableTiming);
    }
    if (!s_attr) {
        cudaFuncSetAttribute(k_gemm_mma<false>,
                             cudaFuncAttributeMaxDynamicSharedMemorySize, GEMM_SMEM_BYTES);
        cudaFuncSetAttribute(k_gemm_mma<true>,
                             cudaFuncAttributeMaxDynamicSharedMemorySize, GEMM_SMEM_BYTES);
        s_attr = true;
    }

    const int TB = 256;
    const int AGG_CTAS = 592;              // 4736 warps, ~10.6 nodes each
    int qblocks = ((E + 3) / 4 + TB - 1) / TB;
    dim3 ggrid(tiles, 2);

    // Fork: CSR build on side stream, overlapped with cvtW + gemm1 on main.
    // Submission order puts gemm1 at kernel #4 (ncu capture window).
    cudaEventRecord(ev_fork, 0);
    cudaStreamWaitEvent(s_csr, ev_fork, 0);
    cudaMemsetAsync(p_counts, 0, (size_t)N * sizeof(int), s_csr);
    cudaMemsetAsync(p_pflag, 0, 64 * sizeof(int), s_csr);
    k_cvtW_all<<<256, TB>>>(W1l, W1r, W2l, W2r);              // #1 (main)
    k_hist<<<qblocks, TB, 0, s_csr>>>(ei, E);                 // #2 (side)
    k_scan_one<<<sblocks, 1024, 0, s_csr>>>(N);               // #3 (side)
    k_gemm_mma<false><<<ggrid, TB, GEMM_SMEM_BYTES>>>(x, b1l, xl, b1r, xr, 0, N); // #4 <- ncu
    k_scatter<<<qblocks, TB, 0, s_csr>>>(ei, E);              // #5 (side)
    cudaEventRecord(ev_join, s_csr);

    cudaStreamWaitEvent(0, ev_join, 0);
    k_agg<false, true, true><<<AGG_CTAS, TB>>>(xl, xr, att1, bias1,
                                               nullptr, Ahp, Alp, N, 0);

    // Layer 2 (A staged from agg1's split-bf16 output)
    k_gemm_mma<true><<<ggrid, TB, GEMM_SMEM_BYTES>>>(nullptr, b2l, xl, b2r, xr, 2, N);
    k_agg<true, false, false><<<AGG_CTAS, TB>>>(xl, xr, att2, bias2,
                                                (float*)d_out, nullptr, nullptr, N, 1);
}

// round 15
// speedup vs baseline: 1.0255x; 1.0255x over previous
#include <cuda_runtime.h>
#include <cuda_bf16.h>
#include <math.h>
#include <stdint.h>

#define NMAX 50176
#define EMAX 800000
#define TILES_MAX 392
#define PITCH 136

typedef unsigned long long u64;

// ---- device scratch (no runtime allocation allowed) ----
__device__ float  g_xl[NMAX * 128];
__device__ float  g_xr[NMAX * 128];
__device__ int    g_counts[NMAX];
__device__ int    g_partial[64];
__device__ int    g_pflag[64];
__device__ int    g_rowptr[NMAX + 1];
__device__ int    g_cursor[NMAX];
__device__ int    g_csrc  [EMAX];
// layer-2 input as split-bf16 in GEMM smem-mirror layout (pitch 136 per 128-row tile)
__device__ unsigned short g_Ah[TILES_MAX * 128 * PITCH];
__device__ unsigned short g_Al[TILES_MAX * 128 * PITCH];
// precomputed W^T split-bf16, packed [n][k]; slots: W1l,W1r,W2l,W2r
__device__ unsigned short g_Bh[4 * 16384];
__device__ unsigned short g_Bl[4 * 16384];

// ---------------- CSR build ----------------
__global__ void k_hist(const int* __restrict__ ei, int E) {
    int t = blockIdx.x * blockDim.x + threadIdx.x;
    int e = t << 2;
    if (e + 3 < E && (E & 3) == 0) {
        int4 d = *(const int4*)(ei + E + e);
        atomicAdd(&g_counts[d.x], 1);
        atomicAdd(&g_counts[d.y], 1);
        atomicAdd(&g_counts[d.z], 1);
        atomicAdd(&g_counts[d.w], 1);
    } else {
        for (int k = e; k < min(e + 4, E); k++)
            atomicAdd(&g_counts[ei[E + k]], 1);
    }
}

// single-kernel scan: warp-shuffle block scan + parallel lookback
__global__ __launch_bounds__(1024) void k_scan_one(int n) {
    __shared__ int wsum[32];
    __shared__ int sh_off;
    int tid = threadIdx.x, b = blockIdx.x;
    int lane = tid & 31, wid = tid >> 5;
    int i = b * 1024 + tid;
    int v = (i < n) ? g_counts[i] : 0;
    int s = v;
#pragma unroll
    for (int o = 1; o < 32; o <<= 1) {
        int t = __shfl_up_sync(0xffffffffu, s, o);
        if (lane >= o) s += t;
    }
    if (lane == 31) wsum[wid] = s;
    __syncthreads();
    if (wid == 0) {
        int ss = wsum[lane];
#pragma unroll
        for (int o = 1; o < 32; o <<= 1) {
            int t = __shfl_up_sync(0xffffffffu, ss, o);
            if (lane >= o) ss += t;
        }
        wsum[lane] = ss;
    }
    __syncthreads();
    int incl = s + (wid ? wsum[wid - 1] : 0);
    if (tid == 1023) {
        g_partial[b] = incl;
        __threadfence();
        atomicExch(&g_pflag[b], 1);
    }
    if (tid < 32) {
        int off = 0;
        for (int j = tid; j < b; j += 32) {
            while (atomicAdd(&g_pflag[j], 0) == 0) { }
            off += atomicAdd(&g_partial[j], 0);
        }
#pragma unroll
        for (int st = 16; st; st >>= 1) off += __shfl_xor_sync(0xffffffffu, off, st);
        if (tid == 0) sh_off = off;
    }
    __syncthreads();
    if (i < n) {
        int gincl = sh_off + incl;
        int excl = gincl - v;
        g_rowptr[i] = excl;
        g_cursor[i] = excl;
        if (i == n - 1) g_rowptr[n] = gincl;
    }
}

__global__ void k_scatter(const int* __restrict__ ei, int E) {
    int t = blockIdx.x * blockDim.x + threadIdx.x;
    int e = t << 2;
    if (e + 3 < E && (E & 3) == 0) {
        int4 s = *(const int4*)(ei + e);
        int4 d = *(const int4*)(ei + E + e);
        g_csrc[atomicAdd(&g_cursor[d.x], 1)] = s.x;
        g_csrc[atomicAdd(&g_cursor[d.y], 1)] = s.y;
        g_csrc[atomicAdd(&g_cursor[d.z], 1)] = s.z;
        g_csrc[atomicAdd(&g_cursor[d.w], 1)] = s.w;
    } else {
        for (int k = e; k < min(e + 4, E); k++)
            g_csrc[atomicAdd(&g_cursor[ei[E + k]], 1)] = ei[k];
    }
}

// ---- split-bf16 helpers ----
__device__ __forceinline__ unsigned short bf_hi(float f) {
    return __bfloat16_as_ushort(__float2bfloat16(f));
}
__device__ __forceinline__ unsigned short bf_lo(float f, unsigned short hi) {
    float fh = __bfloat162float(__ushort_as_bfloat16(hi));
    return __bfloat16_as_ushort(__float2bfloat16(f - fh));
}

// ---------------- one-shot W conversion ----------------
__global__ void k_cvtW_all(const float* __restrict__ W0, const float* __restrict__ W1,
                           const float* __restrict__ W2, const float* __restrict__ W3) {
    int idx = blockIdx.x * blockDim.x + threadIdx.x;
    int slot = idx >> 14;
    int rem = idx & 16383;
    int k = rem >> 7;
    int n = rem & 127;
    const float* W = (slot == 0) ? W0 : (slot == 1) ? W1 : (slot == 2) ? W2 : W3;
    float w = W[rem];
    unsigned short h = bf_hi(w);
    int off = (slot << 14) + (n << 7) + k;
    g_Bh[off] = h;
    g_Bl[off] = bf_lo(w, h);
}

// =================== split-bf16 HMMA GEMM ===================
#define AS_H 0
#define AS_L (128 * PITCH)
#define BS_H (2 * 128 * PITCH)
#define BS_L (3 * 128 * PITCH)
#define GEMM_SMEM_BYTES (4 * 128 * PITCH * 2)
#define A_TILE_U4 2176

__device__ __forceinline__ uint32_t smem_u32(const void* p) {
    uint32_t a;
    asm("{ .reg .u64 t; cvta.to.shared.u64 t, %1; cvt.u32.u64 %0, t; }"
        : "=r"(a) : "l"(p));
    return a;
}

__device__ __forceinline__ void ldsm4(uint32_t& r0, uint32_t& r1, uint32_t& r2,
                                      uint32_t& r3, uint32_t addr) {
    asm volatile("ldmatrix.sync.aligned.m8n8.x4.shared.b16 {%0,%1,%2,%3}, [%4];"
        : "=r"(r0), "=r"(r1), "=r"(r2), "=r"(r3) : "r"(addr));
}

__device__ __forceinline__ void mma16816(float* c, uint32_t a0, uint32_t a1,
                                         uint32_t a2, uint32_t a3,
                                         uint32_t b0, uint32_t b1) {
    asm volatile(
        "mma.sync.aligned.m16n8k16.row.col.f32.bf16.bf16.f32 "
        "{%0,%1,%2,%3}, {%4,%5,%6,%7}, {%8,%9}, {%0,%1,%2,%3};"
        : "+f"(c[0]), "+f"(c[1]), "+f"(c[2]), "+f"(c[3])
        : "r"(a0), "r"(a1), "r"(a2), "r"(a3), "r"(b0), "r"(b1));
}

// ACOPY=false: A converted in-kernel from fp32. ACOPY=true: A copied from g_Ah/g_Al.
// __launch_bounds__(256, 2): cap regs at 128 -> 2 CTAs/SM (fixes occ=12%, regs=255).
template<bool ACOPY>
__global__ __launch_bounds__(256, 2) void k_gemm_mma(
    const float* __restrict__ A,
    const float* __restrict__ bl, float* __restrict__ Cl,
    const float* __restrict__ br, float* __restrict__ Cr,
    int slot0, int M)
{
    extern __shared__ __align__(16) unsigned short sm[];
    int sel = blockIdx.y;
    const float* bias = sel ? br : bl;
    float* C = sel ? Cr : Cl;
    int slot = slot0 + sel;

    int tid = threadIdx.x;
    int row0 = blockIdx.x << 7;

    if (ACOPY) {
        const uint4* sAh = (const uint4*)(g_Ah + (size_t)blockIdx.x * 128 * PITCH);
        const uint4* sAl = (const uint4*)(g_Al + (size_t)blockIdx.x * 128 * PITCH);
        uint4* dAh = (uint4*)(sm + AS_H);
        uint4* dAl = (uint4*)(sm + AS_L);
#pragma unroll 3
        for (int i = 0; i < 9; i++) {
            int p = tid + (i << 8);
            if (p < A_TILE_U4) {
                dAh[p] = sAh[p];
                dAl[p] = sAl[p];
            }
        }
    } else {
        const float4* A4 = (const float4*)(A + (size_t)row0 * 128);
#pragma unroll 4
        for (int i = 0; i < 16; i++) {
            int idx = tid + (i << 8);
            int r = idx >> 5;
            int c = (idx & 31) << 2;
            float4 v = (row0 + r < M) ? A4[idx] : make_float4(0.f, 0.f, 0.f, 0.f);
            ushort4 h, l;
            h.x = bf_hi(v.x); l.x = bf_lo(v.x, h.x);
            h.y = bf_hi(v.y); l.y = bf_lo(v.y, h.y);
            h.z = bf_hi(v.z); l.z = bf_lo(v.z, h.z);
            h.w = bf_hi(v.w); l.w = bf_lo(v.w, h.w);
            *(ushort4*)&sm[AS_H + r * PITCH + c] = h;
            *(ushort4*)&sm[AS_L + r * PITCH + c] = l;
        }
    }
    {
        const uint4* srcH = (const uint4*)(g_Bh + ((size_t)slot << 14));
        const uint4* srcL = (const uint4*)(g_Bl + ((size_t)slot << 14));
#pragma unroll 4
        for (int i = 0; i < 8; i++) {
            int v = tid + (i << 8);
            int e = v << 3;
            int n = e >> 7, k = e & 127;
            int d = n * PITCH + k;
            *(uint4*)&sm[BS_H + d] = srcH[v];
            *(uint4*)&sm[BS_L + d] = srcL[v];
        }
    }
    __syncthreads();

    int wid = tid >> 5, lane = tid & 31;
    int wm = (wid >> 1) << 5;
    int wn = (wid & 1) << 6;

    float acc[2][8][4];
#pragma unroll
    for (int mt = 0; mt < 2; mt++)
#pragma unroll
        for (int nt = 0; nt < 8; nt++)
#pragma unroll
            for (int q = 0; q < 4; q++) acc[mt][nt][q] = 0.f;

    int a_row = lane & 15;
    int a_col = (lane >> 4) << 3;
    int b_row = ((lane >> 4) << 3) + (lane & 7);
    int b_col = ((lane >> 3) & 1) << 3;

    uint32_t sb = smem_u32(sm);
    const int APASS[3] = {AS_H, AS_H, AS_L};
    const int BPASS[3] = {BS_H, BS_L, BS_H};

#pragma unroll 1
    for (int pass = 0; pass < 3; pass++) {
        uint32_t abase = sb + ((uint32_t)(APASS[pass] + (wm + a_row) * PITCH + a_col) << 1);
        uint32_t bbase = sb + ((uint32_t)(BPASS[pass] + (wn + b_row) * PITCH + b_col) << 1);
#pragma unroll
        for (int ks = 0; ks < 8; ks++) {
            int k0 = ks << 4;
            uint32_t af[2][4];
            ldsm4(af[0][0], af[0][1], af[0][2], af[0][3], abase + (k0 << 1));
            ldsm4(af[1][0], af[1][1], af[1][2], af[1][3],
                  abase + (k0 << 1) + (16 * PITCH << 1));
            uint32_t bf[4][4];
#pragma unroll
            for (int g = 0; g < 4; g++)
                ldsm4(bf[g][0], bf[g][1], bf[g][2], bf[g][3],
                      bbase + (k0 << 1) + ((g * 16 * PITCH) << 1));
#pragma unroll
            for (int mt = 0; mt < 2; mt++)
#pragma unroll
                for (int nt = 0; nt < 8; nt++) {
                    uint32_t b0 = bf[nt >> 1][(nt & 1) << 1];
                    uint32_t b1 = bf[nt >> 1][((nt & 1) << 1) + 1];
                    mma16816(acc[mt][nt], af[mt][0], af[mt][1], af[mt][2], af[mt][3], b0, b1);
                }
        }
    }

    int g = lane >> 2, tg = lane & 3;
#pragma unroll
    for (int mt = 0; mt < 2; mt++) {
        int rlo = row0 + wm + (mt << 4) + g;
        int rhi = rlo + 8;
#pragma unroll
        for (int nt = 0; nt < 8; nt++) {
            int col = wn + (nt << 3) + (tg << 1);
            float2 bv = *(const float2*)(bias + col);
            if (rlo < M)
                *(float2*)(C + (size_t)rlo * 128 + col) =
                    make_float2(acc[mt][nt][0] + bv.x, acc[mt][nt][1] + bv.y);
            if (rhi < M)
                *(float2*)(C + (size_t)rhi * 128 + col) =
                    make_float2(acc[mt][nt][2] + bv.x, acc[mt][nt][3] + bv.y);
        }
    }
}

// ---------------- GATv2 aggregation: warp/node, 4 edges/iter (R10 proven) -------
// Exact softmax w/o max-shift (bounded logits); att pre-scaled by log2e; ex2 MUFU.
template<bool FULLWARP, bool DOELU, bool SPLITOUT>
__global__ __launch_bounds__(256) void k_agg(
    const float* __restrict__ xl, const float* __restrict__ xr,
    const float* __restrict__ att, const float* __restrict__ bias,
    float* __restrict__ out, unsigned short* __restrict__ oh,
    unsigned short* __restrict__ ol, int n)
{
    int gw = (blockIdx.x * blockDim.x + threadIdx.x) >> 5;
    if (gw >= n) return;
    int lane = threadIdx.x & 31;
    int node = gw;
    const float LOG2E = 1.4426950408889634f;

    float4 attv = *(const float4*)(att + (lane << 2));
    attv.x *= LOG2E; attv.y *= LOG2E; attv.z *= LOG2E; attv.w *= LOG2E;
    float4 xrv = *(const float4*)(xr + (size_t)node * 128 + (lane << 2));

    int beg = g_rowptr[node];
    int cnt = g_rowptr[node + 1] - beg;

    float denom = 0.f;
    float4 acc = make_float4(0.f, 0.f, 0.f, 0.f);

    const float4* xlp = (const float4*)xl;

#define EDGE_PART(v, part)                                                     \
    {                                                                          \
        float tx = (v).x + xrv.x; tx = fmaxf(tx, 0.2f * tx);                   \
        float ty = (v).y + xrv.y; ty = fmaxf(ty, 0.2f * ty);                   \
        float tz = (v).z + xrv.z; tz = fmaxf(tz, 0.2f * tz);                   \
        float tw = (v).w + xrv.w; tw = fmaxf(tw, 0.2f * tw);                   \
        part = attv.x * tx;                                                    \
        part = fmaf(attv.y, ty, part);                                         \
        part = fmaf(attv.z, tz, part);                                         \
        part = fmaf(attv.w, tw, part);                                         \
    }
#define REDUCE_PART(part)                                                      \
    part += __shfl_xor_sync(0xffffffffu, part, 1);                             \
    part += __shfl_xor_sync(0xffffffffu, part, 2);                             \
    part += __shfl_xor_sync(0xffffffffu, part, 4);                             \
    if (FULLWARP) {                                                            \
        part += __shfl_xor_sync(0xffffffffu, part, 8);                         \
        part += __shfl_xor_sync(0xffffffffu, part, 16);                        \
    }

    // self-loop first
    {
        float4 v = xlp[(size_t)node * 32 + lane];
        float part;
        EDGE_PART(v, part);
        REDUCE_PART(part);
        float p;
        asm("ex2.approx.f32 %0, %1;" : "=f"(p) : "f"(part));
        denom += p;
        acc.x = fmaf(p, v.x, acc.x);
        acc.y = fmaf(p, v.y, acc.y);
        acc.z = fmaf(p, v.z, acc.z);
        acc.w = fmaf(p, v.w, acc.w);
    }

    float4 c0, c1, c2, c3;
    {
        int i0 = (0 < cnt) ? g_csrc[beg + 0] : node;
        int i1 = (1 < cnt) ? g_csrc[beg + 1] : node;
        int i2 = (2 < cnt) ? g_csrc[beg + 2] : node;
        int i3 = (3 < cnt) ? g_csrc[beg + 3] : node;
        c0 = xlp[(size_t)i0 * 32 + lane];
        c1 = xlp[(size_t)i1 * 32 + lane];
        c2 = xlp[(size_t)i2 * 32 + lane];
        c3 = xlp[(size_t)i3 * 32 + lane];
    }

    for (int j = 0; j < cnt; j += 4) {
        float4 n0 = c0, n1 = c1, n2 = c2, n3 = c3;
        int jn = j + 4;
        if (jn < cnt) {
            int i0 = (jn + 0 < cnt) ? g_csrc[beg + jn + 0] : node;
            int i1 = (jn + 1 < cnt) ? g_csrc[beg + jn + 1] : node;
            int i2 = (jn + 2 < cnt) ? g_csrc[beg + jn + 2] : node;
            int i3 = (jn + 3 < cnt) ? g_csrc[beg + jn + 3] : node;
            n0 = xlp[(size_t)i0 * 32 + lane];
            n1 = xlp[(size_t)i1 * 32 + lane];
            n2 = xlp[(size_t)i2 * 32 + lane];
            n3 = xlp[(size_t)i3 * 32 + lane];
        }

        float p0, p1, p2, p3;
        EDGE_PART(c0, p0);
        EDGE_PART(c1, p1);
        EDGE_PART(c2, p2);
        EDGE_PART(c3, p3);
        REDUCE_PART(p0);
        REDUCE_PART(p1);
        REDUCE_PART(p2);
        REDUCE_PART(p3);
        float e0, e1, e2, e3;
        asm("ex2.approx.f32 %0, %1;" : "=f"(e0) : "f"(p0));
        asm("ex2.approx.f32 %0, %1;" : "=f"(e1) : "f"(p1));
        asm("ex2.approx.f32 %0, %1;" : "=f"(e2) : "f"(p2));
        asm("ex2.approx.f32 %0, %1;" : "=f"(e3) : "f"(p3));
        e0 = (j + 0 < cnt) ? e0 : 0.f;
        e1 = (j + 1 < cnt) ? e1 : 0.f;
        e2 = (j + 2 < cnt) ? e2 : 0.f;
        e3 = (j + 3 < cnt) ? e3 : 0.f;

        denom += (e0 + e1) + (e2 + e3);
        acc.x = fmaf(e0, c0.x, fmaf(e1, c1.x, fmaf(e2, c2.x, fmaf(e3, c3.x, acc.x))));
        acc.y = fmaf(e0, c0.y, fmaf(e1, c1.y, fmaf(e2, c2.y, fmaf(e3, c3.y, acc.y))));
        acc.z = fmaf(e0, c0.z, fmaf(e1, c1.z, fmaf(e2, c2.z, fmaf(e3, c3.z, acc.z))));
        acc.w = fmaf(e0, c0.w, fmaf(e1, c1.w, fmaf(e2, c2.w, fmaf(e3, c3.w, acc.w))));

        c0 = n0; c1 = n1; c2 = n2; c3 = n3;
    }
#undef EDGE_PART
#undef REDUCE_PART

    float inv = 1.f / denom;
    float4 bv = *(const float4*)(bias + (lane << 2));
    float ox = fmaf(acc.x, inv, bv.x);
    float oy = fmaf(acc.y, inv, bv.y);
    float oz = fmaf(acc.z, inv, bv.z);
    float ow = fmaf(acc.w, inv, bv.w);
    if (DOELU) {
        ox = ox > 0.f ? ox : __expf(ox) - 1.f;
        oy = oy > 0.f ? oy : __expf(oy) - 1.f;
        oz = oz > 0.f ? oz : __expf(oz) - 1.f;
        ow = ow > 0.f ? ow : __expf(ow) - 1.f;
    }
    if (SPLITOUT) {
        int tile = node >> 7, r = node & 127;
        size_t off = (size_t)tile * 128 * PITCH + r * PITCH + (lane << 2);
        ushort4 hh, ll;
        hh.x = bf_hi(ox); ll.x = bf_lo(ox, hh.x);
        hh.y = bf_hi(oy); ll.y = bf_lo(oy, hh.y);
        hh.z = bf_hi(oz); ll.z = bf_lo(oz, hh.z);
        hh.w = bf_hi(ow); ll.w = bf_lo(ow, hh.w);
        *(ushort4*)&oh[off] = hh;
        *(ushort4*)&ol[off] = ll;
    } else {
        *(float4*)(out + (size_t)node * 128 + (lane << 2)) =
            make_float4(ox, oy, oz, ow);
    }
}

// ---------------- host launcher ----------------
extern "C" void kernel_launch(void* const* d_in, const int* in_sizes, int n_in,
                              void* d_out, int out_size)
{
    const float* x     = (const float*)d_in[0];
    const int*   ei    = (const int*)  d_in[1];
    const float* W1l   = (const float*)d_in[2];
    const float* b1l   = (const float*)d_in[3];
    const float* W1r   = (const float*)d_in[4];
    const float* b1r   = (const float*)d_in[5];
    const float* att1  = (const float*)d_in[6];
    const float* bias1 = (const float*)d_in[7];
    const float* W2l   = (const float*)d_in[8];
    const float* b2l   = (const float*)d_in[9];
    const float* W2r   = (const float*)d_in[10];
    const float* b2r   = (const float*)d_in[11];
    const float* att2  = (const float*)d_in[12];
    const float* bias2 = (const float*)d_in[13];

    int N = in_sizes[0] / 128;
    int E = in_sizes[1] / 2;
    int tiles = (N + 127) / 128;
    int sblocks = (N + 1023) / 1024;

    void *p_xl, *p_xr, *p_Ah, *p_Al, *p_counts, *p_pflag;
    cudaGetSymbolAddress(&p_xl, g_xl);
    cudaGetSymbolAddress(&p_xr, g_xr);
    cudaGetSymbolAddress(&p_Ah, g_Ah);
    cudaGetSymbolAddress(&p_Al, g_Al);
    cudaGetSymbolAddress(&p_counts, g_counts);
    cudaGetSymbolAddress(&p_pflag, g_pflag);
    float* xl = (float*)p_xl;
    float* xr = (float*)p_xr;
    unsigned short* Ahp = (unsigned short*)p_Ah;
    unsigned short* Alp = (unsigned short*)p_Al;

    static cudaStream_t s_csr = nullptr;
    static cudaEvent_t ev_fork = nullptr, ev_join = nullptr;
    static bool s_attr = false;
    if (s_csr == nullptr) {
        cudaStreamCreateWithFlags(&s_csr, cudaStreamNonBlocking);
        cudaEventCreateWithFlags(&ev_fork, cudaEventDisableTiming);
        cudaEventCreateWithFlags(&ev_join, cudaEventDisableTiming);
    }
    if (!s_attr) {
        cudaFuncSetAttribute(k_gemm_mma<false>,
                             cudaFuncAttributeMaxDynamicSharedMemorySize, GEMM_SMEM_BYTES);
        cudaFuncSetAttribute(k_gemm_mma<true>,
                             cudaFuncAttributeMaxDynamicSharedMemorySize, GEMM_SMEM_BYTES);
        s_attr = true;
    }

    const int TB = 256;
    int ablocks = (N * 32 + TB - 1) / TB;
    int qblocks = ((E + 3) / 4 + TB - 1) / TB;
    dim3 ggrid(tiles, 2);

    // Fork: CSR build on side stream, overlapped with cvtW + gemm1 on main.
    // gemm1 stays at kernel #4 (ncu capture window) to verify the occupancy fix.
    cudaEventRecord(ev_fork, 0);
    cudaStreamWaitEvent(s_csr, ev_fork, 0);
    cudaMemsetAsync(p_counts, 0, (size_t)N * sizeof(int), s_csr);
    cudaMemsetAsync(p_pflag, 0, 64 * sizeof(int), s_csr);
    k_cvtW_all<<<256, TB>>>(W1l, W1r, W2l, W2r);              // #1 (main)
    k_hist<<<qblocks, TB, 0, s_csr>>>(ei, E);                 // #2 (side)
    k_scan_one<<<sblocks, 1024, 0, s_csr>>>(N);               // #3 (side)
    k_gemm_mma<false><<<ggrid, TB, GEMM_SMEM_BYTES>>>(x, b1l, xl, b1r, xr, 0, N); // #4 <- ncu
    k_scatter<<<qblocks, TB, 0, s_csr>>>(ei, E);              // #5 (side)
    cudaEventRecord(ev_join, s_csr);

    cudaStreamWaitEvent(0, ev_join, 0);
    k_agg<false, true, true><<<ablocks, TB>>>(xl, xr, att1, bias1,
                                              nullptr, Ahp, Alp, N);

    // Layer 2 (A staged from agg1's split-bf16 output)
    k_gemm_mma<true><<<ggrid, TB, GEMM_SMEM_BYTES>>>(nullptr, b2l, xl, b2r, xr, 2, N);
    k_agg<true, false, false><<<ablocks, TB>>>(xl, xr, att2, bias2,
                                               (float*)d_out, nullptr, nullptr, N);
}

// round 16
// speedup vs baseline: 1.0632x; 1.0368x over previous
#include <cuda_runtime.h>
#include <cuda_bf16.h>
#include <math.h>
#include <stdint.h>

#define NMAX 50176
#define EMAX 800000
#define TILES_MAX 392
#define PITCH 136

typedef unsigned long long u64;

// ---- device scratch (no runtime allocation allowed) ----
__device__ float  g_xl[NMAX * 128];
__device__ float  g_xr[NMAX * 128];
__device__ int    g_counts[NMAX];
__device__ int    g_partial[64];
__device__ int    g_pflag[64];
__device__ int    g_rowptr[NMAX + 1];
__device__ int    g_cursor[NMAX];
__device__ int    g_csrc  [EMAX];
// layer-2 input as split-bf16 in GEMM smem-mirror layout (pitch 136 per 128-row tile)
__device__ unsigned short g_Ah[TILES_MAX * 128 * PITCH];
__device__ unsigned short g_Al[TILES_MAX * 128 * PITCH];
// precomputed W^T split-bf16, packed [n][k]; slots: W1l,W1r,W2l,W2r
__device__ unsigned short g_Bh[4 * 16384];
__device__ unsigned short g_Bl[4 * 16384];

// ---------------- CSR build ----------------
__global__ void k_hist(const int* __restrict__ ei, int E) {
    int t = blockIdx.x * blockDim.x + threadIdx.x;
    int e = t << 2;
    if (e + 3 < E && (E & 3) == 0) {
        int4 d = *(const int4*)(ei + E + e);
        atomicAdd(&g_counts[d.x], 1);
        atomicAdd(&g_counts[d.y], 1);
        atomicAdd(&g_counts[d.z], 1);
        atomicAdd(&g_counts[d.w], 1);
    } else {
        for (int k = e; k < min(e + 4, E); k++)
            atomicAdd(&g_counts[ei[E + k]], 1);
    }
}

// single-kernel scan: warp-shuffle block scan + parallel lookback
__global__ __launch_bounds__(1024) void k_scan_one(int n) {
    __shared__ int wsum[32];
    __shared__ int sh_off;
    int tid = threadIdx.x, b = blockIdx.x;
    int lane = tid & 31, wid = tid >> 5;
    int i = b * 1024 + tid;
    int v = (i < n) ? g_counts[i] : 0;
    int s = v;
#pragma unroll
    for (int o = 1; o < 32; o <<= 1) {
        int t = __shfl_up_sync(0xffffffffu, s, o);
        if (lane >= o) s += t;
    }
    if (lane == 31) wsum[wid] = s;
    __syncthreads();
    if (wid == 0) {
        int ss = wsum[lane];
#pragma unroll
        for (int o = 1; o < 32; o <<= 1) {
            int t = __shfl_up_sync(0xffffffffu, ss, o);
            if (lane >= o) ss += t;
        }
        wsum[lane] = ss;
    }
    __syncthreads();
    int incl = s + (wid ? wsum[wid - 1] : 0);
    if (tid == 1023) {
        g_partial[b] = incl;
        __threadfence();
        atomicExch(&g_pflag[b], 1);
    }
    if (tid < 32) {
        int off = 0;
        for (int j = tid; j < b; j += 32) {
            while (atomicAdd(&g_pflag[j], 0) == 0) { }
            off += atomicAdd(&g_partial[j], 0);
        }
#pragma unroll
        for (int st = 16; st; st >>= 1) off += __shfl_xor_sync(0xffffffffu, off, st);
        if (tid == 0) sh_off = off;
    }
    __syncthreads();
    if (i < n) {
        int gincl = sh_off + incl;
        int excl = gincl - v;
        g_rowptr[i] = excl;
        g_cursor[i] = excl;
        if (i == n - 1) g_rowptr[n] = gincl;
    }
}

__global__ void k_scatter(const int* __restrict__ ei, int E) {
    int t = blockIdx.x * blockDim.x + threadIdx.x;
    int e = t << 2;
    if (e + 3 < E && (E & 3) == 0) {
        int4 s = *(const int4*)(ei + e);
        int4 d = *(const int4*)(ei + E + e);
        g_csrc[atomicAdd(&g_cursor[d.x], 1)] = s.x;
        g_csrc[atomicAdd(&g_cursor[d.y], 1)] = s.y;
        g_csrc[atomicAdd(&g_cursor[d.z], 1)] = s.z;
        g_csrc[atomicAdd(&g_cursor[d.w], 1)] = s.w;
    } else {
        for (int k = e; k < min(e + 4, E); k++)
            g_csrc[atomicAdd(&g_cursor[ei[E + k]], 1)] = ei[k];
    }
}

// ---- split-bf16 helpers ----
__device__ __forceinline__ unsigned short bf_hi(float f) {
    return __bfloat16_as_ushort(__float2bfloat16(f));
}
__device__ __forceinline__ unsigned short bf_lo(float f, unsigned short hi) {
    float fh = __bfloat162float(__ushort_as_bfloat16(hi));
    return __bfloat16_as_ushort(__float2bfloat16(f - fh));
}

// ---------------- one-shot W conversion ----------------
__global__ void k_cvtW_all(const float* __restrict__ W0, const float* __restrict__ W1,
                           const float* __restrict__ W2, const float* __restrict__ W3) {
    int idx = blockIdx.x * blockDim.x + threadIdx.x;
    int slot = idx >> 14;
    int rem = idx & 16383;
    int k = rem >> 7;
    int n = rem & 127;
    const float* W = (slot == 0) ? W0 : (slot == 1) ? W1 : (slot == 2) ? W2 : W3;
    float w = W[rem];
    unsigned short h = bf_hi(w);
    int off = (slot << 14) + (n << 7) + k;
    g_Bh[off] = h;
    g_Bl[off] = bf_lo(w, h);
}

// =================== split-bf16 HMMA GEMM (3-buffer smem: 102KB -> 2 CTAs/SM) ====
// Buffers: T0 = Ah (all passes), T1 = Bh, T2 = Bl (passes 1-2) then Al (pass 3).
#define T0 0
#define T1 (128 * PITCH)
#define T2 (2 * 128 * PITCH)
#define GEMM_SMEM_BYTES (3 * 128 * PITCH * 2)
#define A_TILE_U4 2176

__device__ __forceinline__ uint32_t smem_u32(const void* p) {
    uint32_t a;
    asm("{ .reg .u64 t; cvta.to.shared.u64 t, %1; cvt.u32.u64 %0, t; }"
        : "=r"(a) : "l"(p));
    return a;
}

__device__ __forceinline__ void ldsm4(uint32_t& r0, uint32_t& r1, uint32_t& r2,
                                      uint32_t& r3, uint32_t addr) {
    asm volatile("ldmatrix.sync.aligned.m8n8.x4.shared.b16 {%0,%1,%2,%3}, [%4];"
        : "=r"(r0), "=r"(r1), "=r"(r2), "=r"(r3) : "r"(addr));
}

__device__ __forceinline__ void mma16816(float* c, uint32_t a0, uint32_t a1,
                                         uint32_t a2, uint32_t a3,
                                         uint32_t b0, uint32_t b1) {
    asm volatile(
        "mma.sync.aligned.m16n8k16.row.col.f32.bf16.bf16.f32 "
        "{%0,%1,%2,%3}, {%4,%5,%6,%7}, {%8,%9}, {%0,%1,%2,%3};"
        : "+f"(c[0]), "+f"(c[1]), "+f"(c[2]), "+f"(c[3])
        : "r"(a0), "r"(a1), "r"(a2), "r"(a3), "r"(b0), "r"(b1));
}

// ACOPY=false: A converted in-kernel from fp32. ACOPY=true: A copied from g_Ah/g_Al.
template<bool ACOPY>
__global__ __launch_bounds__(256, 2) void k_gemm_mma(
    const float* __restrict__ A,
    const float* __restrict__ bl, float* __restrict__ Cl,
    const float* __restrict__ br, float* __restrict__ Cr,
    int slot0, int M)
{
    extern __shared__ __align__(16) unsigned short sm[];
    int sel = blockIdx.y;
    const float* bias = sel ? br : bl;
    float* C = sel ? Cr : Cl;
    int slot = slot0 + sel;

    int tid = threadIdx.x;
    int row0 = blockIdx.x << 7;

    // ---- stage 1: Ah -> T0, Bh -> T1, Bl -> T2 ----
    if (ACOPY) {
        const uint4* sAh = (const uint4*)(g_Ah + (size_t)blockIdx.x * 128 * PITCH);
        uint4* dAh = (uint4*)(sm + T0);
#pragma unroll 3
        for (int i = 0; i < 9; i++) {
            int p = tid + (i << 8);
            if (p < A_TILE_U4) dAh[p] = sAh[p];
        }
    } else {
        const float4* A4 = (const float4*)(A + (size_t)row0 * 128);
#pragma unroll 4
        for (int i = 0; i < 16; i++) {
            int idx = tid + (i << 8);
            int r = idx >> 5;
            int c = (idx & 31) << 2;
            float4 v = (row0 + r < M) ? A4[idx] : make_float4(0.f, 0.f, 0.f, 0.f);
            ushort4 h;
            h.x = bf_hi(v.x);
            h.y = bf_hi(v.y);
            h.z = bf_hi(v.z);
            h.w = bf_hi(v.w);
            *(ushort4*)&sm[T0 + r * PITCH + c] = h;
        }
    }
    {
        const uint4* srcH = (const uint4*)(g_Bh + ((size_t)slot << 14));
        const uint4* srcL = (const uint4*)(g_Bl + ((size_t)slot << 14));
#pragma unroll 4
        for (int i = 0; i < 8; i++) {
            int v = tid + (i << 8);
            int e = v << 3;
            int n = e >> 7, k = e & 127;
            int d = n * PITCH + k;
            *(uint4*)&sm[T1 + d] = srcH[v];
            *(uint4*)&sm[T2 + d] = srcL[v];
        }
    }
    __syncthreads();

    int wid = tid >> 5, lane = tid & 31;
    int wm = (wid >> 1) << 5;
    int wn = (wid & 1) << 6;

    float acc[2][8][4];
#pragma unroll
    for (int mt = 0; mt < 2; mt++)
#pragma unroll
        for (int nt = 0; nt < 8; nt++)
#pragma unroll
            for (int q = 0; q < 4; q++) acc[mt][nt][q] = 0.f;

    int a_row = lane & 15;
    int a_col = (lane >> 4) << 3;
    int b_row = ((lane >> 4) << 3) + (lane & 7);
    int b_col = ((lane >> 3) & 1) << 3;

    uint32_t sb = smem_u32(sm);
    uint32_t a_off = ((uint32_t)((wm + a_row) * PITCH + a_col) << 1);
    uint32_t b_off = ((uint32_t)((wn + b_row) * PITCH + b_col) << 1);

#define MAINLOOP_PASS(ABASE, BBASE)                                            \
    {                                                                          \
        uint32_t abase = sb + (uint32_t)((ABASE) << 1) + a_off;                \
        uint32_t bbase = sb + (uint32_t)((BBASE) << 1) + b_off;                \
        _Pragma("unroll")                                                      \
        for (int ks = 0; ks < 8; ks++) {                                       \
            int k0 = ks << 4;                                                  \
            uint32_t af[2][4];                                                 \
            ldsm4(af[0][0], af[0][1], af[0][2], af[0][3], abase + (k0 << 1));  \
            ldsm4(af[1][0], af[1][1], af[1][2], af[1][3],                      \
                  abase + (k0 << 1) + (16 * PITCH << 1));                      \
            uint32_t bf[4][4];                                                 \
            _Pragma("unroll")                                                  \
            for (int g = 0; g < 4; g++)                                        \
                ldsm4(bf[g][0], bf[g][1], bf[g][2], bf[g][3],                  \
                      bbase + (k0 << 1) + ((g * 16 * PITCH) << 1));            \
            _Pragma("unroll")                                                  \
            for (int mt = 0; mt < 2; mt++)                                     \
                _Pragma("unroll")                                              \
                for (int nt = 0; nt < 8; nt++) {                               \
                    uint32_t b0 = bf[nt >> 1][(nt & 1) << 1];                  \
                    uint32_t b1 = bf[nt >> 1][((nt & 1) << 1) + 1];            \
                    mma16816(acc[mt][nt], af[mt][0], af[mt][1],                \
                             af[mt][2], af[mt][3], b0, b1);                    \
                }                                                              \
        }                                                                      \
    }

    MAINLOOP_PASS(T0, T1);   // Ah * Bh
    MAINLOOP_PASS(T0, T2);   // Ah * Bl
    __syncthreads();

    // ---- stage 2: Al -> T2 (overwrite Bl) ----
    if (ACOPY) {
        const uint4* sAl = (const uint4*)(g_Al + (size_t)blockIdx.x * 128 * PITCH);
        uint4* dAl = (uint4*)(sm + T2);
#pragma unroll 3
        for (int i = 0; i < 9; i++) {
            int p = tid + (i << 8);
            if (p < A_TILE_U4) dAl[p] = sAl[p];
        }
    } else {
        const float4* A4 = (const float4*)(A + (size_t)row0 * 128);
#pragma unroll 4
        for (int i = 0; i < 16; i++) {
            int idx = tid + (i << 8);
            int r = idx >> 5;
            int c = (idx & 31) << 2;
            float4 v = (row0 + r < M) ? A4[idx] : make_float4(0.f, 0.f, 0.f, 0.f);
            ushort4 l;
            l.x = bf_lo(v.x, bf_hi(v.x));
            l.y = bf_lo(v.y, bf_hi(v.y));
            l.z = bf_lo(v.z, bf_hi(v.z));
            l.w = bf_lo(v.w, bf_hi(v.w));
            *(ushort4*)&sm[T2 + r * PITCH + c] = l;
        }
    }
    __syncthreads();

    MAINLOOP_PASS(T2, T1);   // Al * Bh
#undef MAINLOOP_PASS

    int g = lane >> 2, tg = lane & 3;
#pragma unroll
    for (int mt = 0; mt < 2; mt++) {
        int rlo = row0 + wm + (mt << 4) + g;
        int rhi = rlo + 8;
#pragma unroll
        for (int nt = 0; nt < 8; nt++) {
            int col = wn + (nt << 3) + (tg << 1);
            float2 bv = *(const float2*)(bias + col);
            if (rlo < M)
                *(float2*)(C + (size_t)rlo * 128 + col) =
                    make_float2(acc[mt][nt][0] + bv.x, acc[mt][nt][1] + bv.y);
            if (rhi < M)
                *(float2*)(C + (size_t)rhi * 128 + col) =
                    make_float2(acc[mt][nt][2] + bv.x, acc[mt][nt][3] + bv.y);
        }
    }
}

// ---------------- GATv2 aggregation: warp/node, 4 edges/iter (R10 proven) -------
template<bool FULLWARP, bool DOELU, bool SPLITOUT>
__global__ __launch_bounds__(256) void k_agg(
    const float* __restrict__ xl, const float* __restrict__ xr,
    const float* __restrict__ att, const float* __restrict__ bias,
    float* __restrict__ out, unsigned short* __restrict__ oh,
    unsigned short* __restrict__ ol, int n)
{
    int gw = (blockIdx.x * blockDim.x + threadIdx.x) >> 5;
    if (gw >= n) return;
    int lane = threadIdx.x & 31;
    int node = gw;
    const float LOG2E = 1.4426950408889634f;

    float4 attv = *(const float4*)(att + (lane << 2));
    attv.x *= LOG2E; attv.y *= LOG2E; attv.z *= LOG2E; attv.w *= LOG2E;
    float4 xrv = *(const float4*)(xr + (size_t)node * 128 + (lane << 2));

    int beg = g_rowptr[node];
    int cnt = g_rowptr[node + 1] - beg;

    float denom = 0.f;
    float4 acc = make_float4(0.f, 0.f, 0.f, 0.f);

    const float4* xlp = (const float4*)xl;

#define EDGE_PART(v, part)                                                     \
    {                                                                          \
        float tx = (v).x + xrv.x; tx = fmaxf(tx, 0.2f * tx);                   \
        float ty = (v).y + xrv.y; ty = fmaxf(ty, 0.2f * ty);                   \
        float tz = (v).z + xrv.z; tz = fmaxf(tz, 0.2f * tz);                   \
        float tw = (v).w + xrv.w; tw = fmaxf(tw, 0.2f * tw);                   \
        part = attv.x * tx;                                                    \
        part = fmaf(attv.y, ty, part);                                         \
        part = fmaf(attv.z, tz, part);                                         \
        part = fmaf(attv.w, tw, part);                                         \
    }
#define REDUCE_PART(part)                                                      \
    part += __shfl_xor_sync(0xffffffffu, part, 1);                             \
    part += __shfl_xor_sync(0xffffffffu, part, 2);                             \
    part += __shfl_xor_sync(0xffffffffu, part, 4);                             \
    if (FULLWARP) {                                                            \
        part += __shfl_xor_sync(0xffffffffu, part, 8);                         \
        part += __shfl_xor_sync(0xffffffffu, part, 16);                        \
    }

    // self-loop first
    {
        float4 v = xlp[(size_t)node * 32 + lane];
        float part;
        EDGE_PART(v, part);
        REDUCE_PART(part);
        float p;
        asm("ex2.approx.f32 %0, %1;" : "=f"(p) : "f"(part));
        denom += p;
        acc.x = fmaf(p, v.x, acc.x);
        acc.y = fmaf(p, v.y, acc.y);
        acc.z = fmaf(p, v.z, acc.z);
        acc.w = fmaf(p, v.w, acc.w);
    }

    float4 c0, c1, c2, c3;
    {
        int i0 = (0 < cnt) ? g_csrc[beg + 0] : node;
        int i1 = (1 < cnt) ? g_csrc[beg + 1] : node;
        int i2 = (2 < cnt) ? g_csrc[beg + 2] : node;
        int i3 = (3 < cnt) ? g_csrc[beg + 3] : node;
        c0 = xlp[(size_t)i0 * 32 + lane];
        c1 = xlp[(size_t)i1 * 32 + lane];
        c2 = xlp[(size_t)i2 * 32 + lane];
        c3 = xlp[(size_t)i3 * 32 + lane];
    }

    for (int j = 0; j < cnt; j += 4) {
        float4 n0 = c0, n1 = c1, n2 = c2, n3 = c3;
        int jn = j + 4;
        if (jn < cnt) {
            int i0 = (jn + 0 < cnt) ? g_csrc[beg + jn + 0] : node;
            int i1 = (jn + 1 < cnt) ? g_csrc[beg + jn + 1] : node;
            int i2 = (jn + 2 < cnt) ? g_csrc[beg + jn + 2] : node;
            int i3 = (jn + 3 < cnt) ? g_csrc[beg + jn + 3] : node;
            n0 = xlp[(size_t)i0 * 32 + lane];
            n1 = xlp[(size_t)i1 * 32 + lane];
            n2 = xlp[(size_t)i2 * 32 + lane];
            n3 = xlp[(size_t)i3 * 32 + lane];
        }

        float p0, p1, p2, p3;
        EDGE_PART(c0, p0);
        EDGE_PART(c1, p1);
        EDGE_PART(c2, p2);
        EDGE_PART(c3, p3);
        REDUCE_PART(p0);
        REDUCE_PART(p1);
        REDUCE_PART(p2);
        REDUCE_PART(p3);
        float e0, e1, e2, e3;
        asm("ex2.approx.f32 %0, %1;" : "=f"(e0) : "f"(p0));
        asm("ex2.approx.f32 %0, %1;" : "=f"(e1) : "f"(p1));
        asm("ex2.approx.f32 %0, %1;" : "=f"(e2) : "f"(p2));
        asm("ex2.approx.f32 %0, %1;" : "=f"(e3) : "f"(p3));
        e0 = (j + 0 < cnt) ? e0 : 0.f;
        e1 = (j + 1 < cnt) ? e1 : 0.f;
        e2 = (j + 2 < cnt) ? e2 : 0.f;
        e3 = (j + 3 < cnt) ? e3 : 0.f;

        denom += (e0 + e1) + (e2 + e3);
        acc.x = fmaf(e0, c0.x, fmaf(e1, c1.x, fmaf(e2, c2.x, fmaf(e3, c3.x, acc.x))));
        acc.y = fmaf(e0, c0.y, fmaf(e1, c1.y, fmaf(e2, c2.y, fmaf(e3, c3.y, acc.y))));
        acc.z = fmaf(e0, c0.z, fmaf(e1, c1.z, fmaf(e2, c2.z, fmaf(e3, c3.z, acc.z))));
        acc.w = fmaf(e0, c0.w, fmaf(e1, c1.w, fmaf(e2, c2.w, fmaf(e3, c3.w, acc.w))));

        c0 = n0; c1 = n1; c2 = n2; c3 = n3;
    }
#undef EDGE_PART
#undef REDUCE_PART

    float inv = 1.f / denom;
    float4 bv = *(const float4*)(bias + (lane << 2));
    float ox = fmaf(acc.x, inv, bv.x);
    float oy = fmaf(acc.y, inv, bv.y);
    float oz = fmaf(acc.z, inv, bv.z);
    float ow = fmaf(acc.w, inv, bv.w);
    if (DOELU) {
        ox = ox > 0.f ? ox : __expf(ox) - 1.f;
        oy = oy > 0.f ? oy : __expf(oy) - 1.f;
        oz = oz > 0.f ? oz : __expf(oz) - 1.f;
        ow = ow > 0.f ? ow : __expf(ow) - 1.f;
    }
    if (SPLITOUT) {
        int tile = node >> 7, r = node & 127;
        size_t off = (size_t)tile * 128 * PITCH + r * PITCH + (lane << 2);
        ushort4 hh, ll;
        hh.x = bf_hi(ox); ll.x = bf_lo(ox, hh.x);
        hh.y = bf_hi(oy); ll.y = bf_lo(oy, hh.y);
        hh.z = bf_hi(oz); ll.z = bf_lo(oz, hh.z);
        hh.w = bf_hi(ow); ll.w = bf_lo(ow, hh.w);
        *(ushort4*)&oh[off] = hh;
        *(ushort4*)&ol[off] = ll;
    } else {
        *(float4*)(out + (size_t)node * 128 + (lane << 2)) =
            make_float4(ox, oy, oz, ow);
    }
}

// ---------------- host launcher ----------------
extern "C" void kernel_launch(void* const* d_in, const int* in_sizes, int n_in,
                              void* d_out, int out_size)
{
    const float* x     = (const float*)d_in[0];
    const int*   ei    = (const int*)  d_in[1];
    const float* W1l   = (const float*)d_in[2];
    const float* b1l   = (const float*)d_in[3];
    const float* W1r   = (const float*)d_in[4];
    const float* b1r   = (const float*)d_in[5];
    const float* att1  = (const float*)d_in[6];
    const float* bias1 = (const float*)d_in[7];
    const float* W2l   = (const float*)d_in[8];
    const float* b2l   = (const float*)d_in[9];
    const float* W2r   = (const float*)d_in[10];
    const float* b2r   = (const float*)d_in[11];
    const float* att2  = (const float*)d_in[12];
    const float* bias2 = (const float*)d_in[13];

    int N = in_sizes[0] / 128;
    int E = in_sizes[1] / 2;
    int tiles = (N + 127) / 128;
    int sblocks = (N + 1023) / 1024;

    void *p_xl, *p_xr, *p_Ah, *p_Al, *p_counts, *p_pflag;
    cudaGetSymbolAddress(&p_xl, g_xl);
    cudaGetSymbolAddress(&p_xr, g_xr);
    cudaGetSymbolAddress(&p_Ah, g_Ah);
    cudaGetSymbolAddress(&p_Al, g_Al);
    cudaGetSymbolAddress(&p_counts, g_counts);
    cudaGetSymbolAddress(&p_pflag, g_pflag);
    float* xl = (float*)p_xl;
    float* xr = (float*)p_xr;
    unsigned short* Ahp = (unsigned short*)p_Ah;
    unsigned short* Alp = (unsigned short*)p_Al;

    static cudaStream_t s_csr = nullptr;
    static cudaEvent_t ev_fork = nullptr, ev_join = nullptr;
    static bool s_attr = false;
    if (s_csr == nullptr) {
        cudaStreamCreateWithFlags(&s_csr, cudaStreamNonBlocking);
        cudaEventCreateWithFlags(&ev_fork, cudaEventDisableTiming);
        cudaEventCreateWithFlags(&ev_join, cudaEventDisableTiming);
    }
    if (!s_attr) {
        cudaFuncSetAttribute(k_gemm_mma<false>,
                             cudaFuncAttributeMaxDynamicSharedMemorySize, GEMM_SMEM_BYTES);
        cudaFuncSetAttribute(k_gemm_mma<true>,
                             cudaFuncAttributeMaxDynamicSharedMemorySize, GEMM_SMEM_BYTES);
        s_attr = true;
    }

    const int TB = 256;
    int ablocks = (N * 32 + TB - 1) / TB;
    int qblocks = ((E + 3) / 4 + TB - 1) / TB;
    dim3 ggrid(tiles, 2);

    // Fork: CSR build on side stream, overlapped with cvtW + gemm1 on main.
    // gemm1 stays at kernel #4 (ncu capture window) to verify the smem fix.
    cudaEventRecord(ev_fork, 0);
    cudaStreamWaitEvent(s_csr, ev_fork, 0);
    cudaMemsetAsync(p_counts, 0, (size_t)N * sizeof(int), s_csr);
    cudaMemsetAsync(p_pflag, 0, 64 * sizeof(int), s_csr);
    k_cvtW_all<<<256, TB>>>(W1l, W1r, W2l, W2r);              // #1 (main)
    k_hist<<<qblocks, TB, 0, s_csr>>>(ei, E);                 // #2 (side)
    k_scan_one<<<sblocks, 1024, 0, s_csr>>>(N);               // #3 (side)
    k_gemm_mma<false><<<ggrid, TB, GEMM_SMEM_BYTES>>>(x, b1l, xl, b1r, xr, 0, N); // #4 <- ncu
    k_scatter<<<qblocks, TB, 0, s_csr>>>(ei, E);              // #5 (side)
    cudaEventRecord(ev_join, s_csr);

    cudaStreamWaitEvent(0, ev_join, 0);
    k_agg<false, true, true><<<ablocks, TB>>>(xl, xr, att1, bias1,
                                              nullptr, Ahp, Alp, N);

    // Layer 2 (A staged from agg1's split-bf16 output)
    k_gemm_mma<true><<<ggrid, TB, GEMM_SMEM_BYTES>>>(nullptr, b2l, xl, b2r, xr, 2, N);
    k_agg<true, false, false><<<ablocks, TB>>>(xl, xr, att2, bias2,
                                               (float*)d_out, nullptr, nullptr, N);
}

// round 17
// speedup vs baseline: 1.1742x; 1.1043x over previous
#include <cuda_runtime.h>
#include <cuda_fp16.h>
#include <math.h>
#include <stdint.h>

#define NMAX 50176
#define EMAX 800000
#define TILES_MAX 392
#define PITCH 136

typedef unsigned long long u64;

// ---- device scratch (no runtime allocation allowed) ----
__device__ float  g_xl[NMAX * 128];
__device__ float  g_xr[NMAX * 128];
__device__ int    g_counts[NMAX];
__device__ int    g_partial[64];
__device__ int    g_pflag[64];
__device__ int    g_rowptr[NMAX + 1];
__device__ int    g_cursor[NMAX];
__device__ int    g_csrc  [EMAX];
// layer-2 input as fp16 in GEMM smem-mirror layout (pitch 136 per 128-row tile)
__device__ unsigned short g_Ah[TILES_MAX * 128 * PITCH];
// precomputed W^T split-fp16, packed [n][k]; slots: W1l,W1r,W2l,W2r
__device__ unsigned short g_Bh[4 * 16384];
__device__ unsigned short g_Bl[4 * 16384];

// ---------------- CSR build ----------------
__global__ void k_hist(const int* __restrict__ ei, int E) {
    int t = blockIdx.x * blockDim.x + threadIdx.x;
    int e = t << 2;
    if (e + 3 < E && (E & 3) == 0) {
        int4 d = *(const int4*)(ei + E + e);
        atomicAdd(&g_counts[d.x], 1);
        atomicAdd(&g_counts[d.y], 1);
        atomicAdd(&g_counts[d.z], 1);
        atomicAdd(&g_counts[d.w], 1);
    } else {
        for (int k = e; k < min(e + 4, E); k++)
            atomicAdd(&g_counts[ei[E + k]], 1);
    }
}

__global__ __launch_bounds__(1024) void k_scan_one(int n) {
    __shared__ int wsum[32];
    __shared__ int sh_off;
    int tid = threadIdx.x, b = blockIdx.x;
    int lane = tid & 31, wid = tid >> 5;
    int i = b * 1024 + tid;
    int v = (i < n) ? g_counts[i] : 0;
    int s = v;
#pragma unroll
    for (int o = 1; o < 32; o <<= 1) {
        int t = __shfl_up_sync(0xffffffffu, s, o);
        if (lane >= o) s += t;
    }
    if (lane == 31) wsum[wid] = s;
    __syncthreads();
    if (wid == 0) {
        int ss = wsum[lane];
#pragma unroll
        for (int o = 1; o < 32; o <<= 1) {
            int t = __shfl_up_sync(0xffffffffu, ss, o);
            if (lane >= o) ss += t;
        }
        wsum[lane] = ss;
    }
    __syncthreads();
    int incl = s + (wid ? wsum[wid - 1] : 0);
    if (tid == 1023) {
        g_partial[b] = incl;
        __threadfence();
        atomicExch(&g_pflag[b], 1);
    }
    if (tid < 32) {
        int off = 0;
        for (int j = tid; j < b; j += 32) {
            while (atomicAdd(&g_pflag[j], 0) == 0) { }
            off += atomicAdd(&g_partial[j], 0);
        }
#pragma unroll
        for (int st = 16; st; st >>= 1) off += __shfl_xor_sync(0xffffffffu, off, st);
        if (tid == 0) sh_off = off;
    }
    __syncthreads();
    if (i < n) {
        int gincl = sh_off + incl;
        int excl = gincl - v;
        g_rowptr[i] = excl;
        g_cursor[i] = excl;
        if (i == n - 1) g_rowptr[n] = gincl;
    }
}

__global__ void k_scatter(const int* __restrict__ ei, int E) {
    int t = blockIdx.x * blockDim.x + threadIdx.x;
    int e = t << 2;
    if (e + 3 < E && (E & 3) == 0) {
        int4 s = *(const int4*)(ei + e);
        int4 d = *(const int4*)(ei + E + e);
        g_csrc[atomicAdd(&g_cursor[d.x], 1)] = s.x;
        g_csrc[atomicAdd(&g_cursor[d.y], 1)] = s.y;
        g_csrc[atomicAdd(&g_cursor[d.z], 1)] = s.z;
        g_csrc[atomicAdd(&g_cursor[d.w], 1)] = s.w;
    } else {
        for (int k = e; k < min(e + 4, E); k++)
            g_csrc[atomicAdd(&g_cursor[ei[E + k]], 1)] = ei[k];
    }
}

// ---- fp16 helpers ----
__device__ __forceinline__ unsigned short hp(float f) {
    return __half_as_ushort(__float2half_rn(f));
}
__device__ __forceinline__ unsigned short hp_lo(float f, unsigned short hi) {
    float fh = __half2float(__ushort_as_half(hi));
    return __half_as_ushort(__float2half_rn(f - fh));
}

// ---------------- one-shot W conversion: B=W^T split-fp16 ----------------
__global__ void k_cvtW_all(const float* __restrict__ W0, const float* __restrict__ W1,
                           const float* __restrict__ W2, const float* __restrict__ W3) {
    int idx = blockIdx.x * blockDim.x + threadIdx.x;
    int slot = idx >> 14;
    int rem = idx & 16383;
    int k = rem >> 7;
    int n = rem & 127;
    const float* W = (slot == 0) ? W0 : (slot == 1) ? W1 : (slot == 2) ? W2 : W3;
    float w = W[rem];
    unsigned short h = hp(w);
    int off = (slot << 14) + (n << 7) + k;
    g_Bh[off] = h;
    g_Bl[off] = hp_lo(w, h);
}

// =================== split-fp16 HMMA GEMM (2 passes: Ah*Bh + Ah*Bl) ============
// Buffers: T0 = Ah, T1 = Bh, T2 = Bl. 102KB smem -> 2 CTAs/SM; no restage.
#define T0 0
#define T1 (128 * PITCH)
#define T2 (2 * 128 * PITCH)
#define GEMM_SMEM_BYTES (3 * 128 * PITCH * 2)
#define A_TILE_U4 2176

__device__ __forceinline__ uint32_t smem_u32(const void* p) {
    uint32_t a;
    asm("{ .reg .u64 t; cvta.to.shared.u64 t, %1; cvt.u32.u64 %0, t; }"
        : "=r"(a) : "l"(p));
    return a;
}

__device__ __forceinline__ void ldsm4(uint32_t& r0, uint32_t& r1, uint32_t& r2,
                                      uint32_t& r3, uint32_t addr) {
    asm volatile("ldmatrix.sync.aligned.m8n8.x4.shared.b16 {%0,%1,%2,%3}, [%4];"
        : "=r"(r0), "=r"(r1), "=r"(r2), "=r"(r3) : "r"(addr));
}

__device__ __forceinline__ void mma16816(float* c, uint32_t a0, uint32_t a1,
                                         uint32_t a2, uint32_t a3,
                                         uint32_t b0, uint32_t b1) {
    asm volatile(
        "mma.sync.aligned.m16n8k16.row.col.f32.f16.f16.f32 "
        "{%0,%1,%2,%3}, {%4,%5,%6,%7}, {%8,%9}, {%0,%1,%2,%3};"
        : "+f"(c[0]), "+f"(c[1]), "+f"(c[2]), "+f"(c[3])
        : "r"(a0), "r"(a1), "r"(a2), "r"(a3), "r"(b0), "r"(b1));
}

// ACOPY=false: A converted in-kernel from fp32. ACOPY=true: A copied from g_Ah.
template<bool ACOPY>
__global__ __launch_bounds__(256, 2) void k_gemm_mma(
    const float* __restrict__ A,
    const float* __restrict__ bl, float* __restrict__ Cl,
    const float* __restrict__ br, float* __restrict__ Cr,
    int slot0, int M)
{
    extern __shared__ __align__(16) unsigned short sm[];
    int sel = blockIdx.y;
    const float* bias = sel ? br : bl;
    float* C = sel ? Cr : Cl;
    int slot = slot0 + sel;

    int tid = threadIdx.x;
    int row0 = blockIdx.x << 7;

    // ---- stage: Ah -> T0, Bh -> T1, Bl -> T2 ----
    if (ACOPY) {
        const uint4* sAh = (const uint4*)(g_Ah + (size_t)blockIdx.x * 128 * PITCH);
        uint4* dAh = (uint4*)(sm + T0);
#pragma unroll 3
        for (int i = 0; i < 9; i++) {
            int p = tid + (i << 8);
            if (p < A_TILE_U4) dAh[p] = sAh[p];
        }
    } else {
        const float4* A4 = (const float4*)(A + (size_t)row0 * 128);
#pragma unroll 4
        for (int i = 0; i < 16; i++) {
            int idx = tid + (i << 8);
            int r = idx >> 5;
            int c = (idx & 31) << 2;
            float4 v = (row0 + r < M) ? A4[idx] : make_float4(0.f, 0.f, 0.f, 0.f);
            ushort4 h;
            h.x = hp(v.x);
            h.y = hp(v.y);
            h.z = hp(v.z);
            h.w = hp(v.w);
            *(ushort4*)&sm[T0 + r * PITCH + c] = h;
        }
    }
    {
        const uint4* srcH = (const uint4*)(g_Bh + ((size_t)slot << 14));
        const uint4* srcL = (const uint4*)(g_Bl + ((size_t)slot << 14));
#pragma unroll 4
        for (int i = 0; i < 8; i++) {
            int v = tid + (i << 8);
            int e = v << 3;
            int n = e >> 7, k = e & 127;
            int d = n * PITCH + k;
            *(uint4*)&sm[T1 + d] = srcH[v];
            *(uint4*)&sm[T2 + d] = srcL[v];
        }
    }
    __syncthreads();

    int wid = tid >> 5, lane = tid & 31;
    int wm = (wid >> 1) << 5;
    int wn = (wid & 1) << 6;

    float acc[2][8][4];
#pragma unroll
    for (int mt = 0; mt < 2; mt++)
#pragma unroll
        for (int nt = 0; nt < 8; nt++)
#pragma unroll
            for (int q = 0; q < 4; q++) acc[mt][nt][q] = 0.f;

    int a_row = lane & 15;
    int a_col = (lane >> 4) << 3;
    int b_row = ((lane >> 4) << 3) + (lane & 7);
    int b_col = ((lane >> 3) & 1) << 3;

    uint32_t sb = smem_u32(sm);
    uint32_t a_off = ((uint32_t)((wm + a_row) * PITCH + a_col) << 1);
    uint32_t b_off = ((uint32_t)((wn + b_row) * PITCH + b_col) << 1);

#define MAINLOOP_PASS(ABASE, BBASE)                                            \
    {                                                                          \
        uint32_t abase = sb + (uint32_t)((ABASE) << 1) + a_off;                \
        uint32_t bbase = sb + (uint32_t)((BBASE) << 1) + b_off;                \
        _Pragma("unroll")                                                      \
        for (int ks = 0; ks < 8; ks++) {                                       \
            int k0 = ks << 4;                                                  \
            uint32_t af[2][4];                                                 \
            ldsm4(af[0][0], af[0][1], af[0][2], af[0][3], abase + (k0 << 1));  \
            ldsm4(af[1][0], af[1][1], af[1][2], af[1][3],                      \
                  abase + (k0 << 1) + (16 * PITCH << 1));                      \
            uint32_t bf[4][4];                                                 \
            _Pragma("unroll")                                                  \
            for (int g = 0; g < 4; g++)                                        \
                ldsm4(bf[g][0], bf[g][1], bf[g][2], bf[g][3],                  \
                      bbase + (k0 << 1) + ((g * 16 * PITCH) << 1));            \
            _Pragma("unroll")                                                  \
            for (int mt = 0; mt < 2; mt++)                                     \
                _Pragma("unroll")                                              \
                for (int nt = 0; nt < 8; nt++) {                               \
                    uint32_t b0 = bf[nt >> 1][(nt & 1) << 1];                  \
                    uint32_t b1 = bf[nt >> 1][((nt & 1) << 1) + 1];            \
                    mma16816(acc[mt][nt], af[mt][0], af[mt][1],                \
                             af[mt][2], af[mt][3], b0, b1);                    \
                }                                                              \
        }                                                                      \
    }

    MAINLOOP_PASS(T0, T1);   // Ah * Bh
    MAINLOOP_PASS(T0, T2);   // Ah * Bl
#undef MAINLOOP_PASS

    int g = lane >> 2, tg = lane & 3;
#pragma unroll
    for (int mt = 0; mt < 2; mt++) {
        int rlo = row0 + wm + (mt << 4) + g;
        int rhi = rlo + 8;
#pragma unroll
        for (int nt = 0; nt < 8; nt++) {
            int col = wn + (nt << 3) + (tg << 1);
            float2 bv = *(const float2*)(bias + col);
            if (rlo < M)
                *(float2*)(C + (size_t)rlo * 128 + col) =
                    make_float2(acc[mt][nt][0] + bv.x, acc[mt][nt][1] + bv.y);
            if (rhi < M)
                *(float2*)(C + (size_t)rhi * 128 + col) =
                    make_float2(acc[mt][nt][2] + bv.x, acc[mt][nt][3] + bv.y);
        }
    }
}

// ---------------- GATv2 aggregation: warp/node, 4 edges/iter (R10 proven) -------
template<bool FULLWARP, bool DOELU, bool SPLITOUT>
__global__ __launch_bounds__(256) void k_agg(
    const float* __restrict__ xl, const float* __restrict__ xr,
    const float* __restrict__ att, const float* __restrict__ bias,
    float* __restrict__ out, unsigned short* __restrict__ oh, int n)
{
    int gw = (blockIdx.x * blockDim.x + threadIdx.x) >> 5;
    if (gw >= n) return;
    int lane = threadIdx.x & 31;
    int node = gw;
    const float LOG2E = 1.4426950408889634f;

    float4 attv = *(const float4*)(att + (lane << 2));
    attv.x *= LOG2E; attv.y *= LOG2E; attv.z *= LOG2E; attv.w *= LOG2E;
    float4 xrv = *(const float4*)(xr + (size_t)node * 128 + (lane << 2));

    int beg = g_rowptr[node];
    int cnt = g_rowptr[node + 1] - beg;

    float denom = 0.f;
    float4 acc = make_float4(0.f, 0.f, 0.f, 0.f);

    const float4* xlp = (const float4*)xl;

#define EDGE_PART(v, part)                                                     \
    {                                                                          \
        float tx = (v).x + xrv.x; tx = fmaxf(tx, 0.2f * tx);                   \
        float ty = (v).y + xrv.y; ty = fmaxf(ty, 0.2f * ty);                   \
        float tz = (v).z + xrv.z; tz = fmaxf(tz, 0.2f * tz);                   \
        float tw = (v).w + xrv.w; tw = fmaxf(tw, 0.2f * tw);                   \
        part = attv.x * tx;                                                    \
        part = fmaf(attv.y, ty, part);                                         \
        part = fmaf(attv.z, tz, part);                                         \
        part = fmaf(attv.w, tw, part);                                         \
    }
#define REDUCE_PART(part)                                                      \
    part += __shfl_xor_sync(0xffffffffu, part, 1);                             \
    part += __shfl_xor_sync(0xffffffffu, part, 2);                             \
    part += __shfl_xor_sync(0xffffffffu, part, 4);                             \
    if (FULLWARP) {                                                            \
        part += __shfl_xor_sync(0xffffffffu, part, 8);                         \
        part += __shfl_xor_sync(0xffffffffu, part, 16);                        \
    }

    // self-loop first
    {
        float4 v = xlp[(size_t)node * 32 + lane];
        float part;
        EDGE_PART(v, part);
        REDUCE_PART(part);
        float p;
        asm("ex2.approx.f32 %0, %1;" : "=f"(p) : "f"(part));
        denom += p;
        acc.x = fmaf(p, v.x, acc.x);
        acc.y = fmaf(p, v.y, acc.y);
        acc.z = fmaf(p, v.z, acc.z);
        acc.w = fmaf(p, v.w, acc.w);
    }

    float4 c0, c1, c2, c3;
    {
        int i0 = (0 < cnt) ? g_csrc[beg + 0] : node;
        int i1 = (1 < cnt) ? g_csrc[beg + 1] : node;
        int i2 = (2 < cnt) ? g_csrc[beg + 2] : node;
        int i3 = (3 < cnt) ? g_csrc[beg + 3] : node;
        c0 = xlp[(size_t)i0 * 32 + lane];
        c1 = xlp[(size_t)i1 * 32 + lane];
        c2 = xlp[(size_t)i2 * 32 + lane];
        c3 = xlp[(size_t)i3 * 32 + lane];
    }

    for (int j = 0; j < cnt; j += 4) {
        float4 n0 = c0, n1 = c1, n2 = c2, n3 = c3;
        int jn = j + 4;
        if (jn < cnt) {
            int i0 = (jn + 0 < cnt) ? g_csrc[beg + jn + 0] : node;
            int i1 = (jn + 1 < cnt) ? g_csrc[beg + jn + 1] : node;
            int i2 = (jn + 2 < cnt) ? g_csrc[beg + jn + 2] : node;
            int i3 = (jn + 3 < cnt) ? g_csrc[beg + jn + 3] : node;
            n0 = xlp[(size_t)i0 * 32 + lane];
            n1 = xlp[(size_t)i1 * 32 + lane];
            n2 = xlp[(size_t)i2 * 32 + lane];
            n3 = xlp[(size_t)i3 * 32 + lane];
        }

        float p0, p1, p2, p3;
        EDGE_PART(c0, p0);
        EDGE_PART(c1, p1);
        EDGE_PART(c2, p2);
        EDGE_PART(c3, p3);
        REDUCE_PART(p0);
        REDUCE_PART(p1);
        REDUCE_PART(p2);
        REDUCE_PART(p3);
        float e0, e1, e2, e3;
        asm("ex2.approx.f32 %0, %1;" : "=f"(e0) : "f"(p0));
        asm("ex2.approx.f32 %0, %1;" : "=f"(e1) : "f"(p1));
        asm("ex2.approx.f32 %0, %1;" : "=f"(e2) : "f"(p2));
        asm("ex2.approx.f32 %0, %1;" : "=f"(e3) : "f"(p3));
        e0 = (j + 0 < cnt) ? e0 : 0.f;
        e1 = (j + 1 < cnt) ? e1 : 0.f;
        e2 = (j + 2 < cnt) ? e2 : 0.f;
        e3 = (j + 3 < cnt) ? e3 : 0.f;

        denom += (e0 + e1) + (e2 + e3);
        acc.x = fmaf(e0, c0.x, fmaf(e1, c1.x, fmaf(e2, c2.x, fmaf(e3, c3.x, acc.x))));
        acc.y = fmaf(e0, c0.y, fmaf(e1, c1.y, fmaf(e2, c2.y, fmaf(e3, c3.y, acc.y))));
        acc.z = fmaf(e0, c0.z, fmaf(e1, c1.z, fmaf(e2, c2.z, fmaf(e3, c3.z, acc.z))));
        acc.w = fmaf(e0, c0.w, fmaf(e1, c1.w, fmaf(e2, c2.w, fmaf(e3, c3.w, acc.w))));

        c0 = n0; c1 = n1; c2 = n2; c3 = n3;
    }
#undef EDGE_PART
#undef REDUCE_PART

    float inv = 1.f / denom;
    float4 bv = *(const float4*)(bias + (lane << 2));
    float ox = fmaf(acc.x, inv, bv.x);
    float oy = fmaf(acc.y, inv, bv.y);
    float oz = fmaf(acc.z, inv, bv.z);
    float ow = fmaf(acc.w, inv, bv.w);
    if (DOELU) {
        ox = ox > 0.f ? ox : __expf(ox) - 1.f;
        oy = oy > 0.f ? oy : __expf(oy) - 1.f;
        oz = oz > 0.f ? oz : __expf(oz) - 1.f;
        ow = ow > 0.f ? ow : __expf(ow) - 1.f;
    }
    if (SPLITOUT) {
        // write fp16 directly in GEMM's pitch-136 tile layout (Ah only)
        int tile = node >> 7, r = node & 127;
        size_t off = (size_t)tile * 128 * PITCH + r * PITCH + (lane << 2);
        ushort4 hh;
        hh.x = hp(ox);
        hh.y = hp(oy);
        hh.z = hp(oz);
        hh.w = hp(ow);
        *(ushort4*)&oh[off] = hh;
    } else {
        *(float4*)(out + (size_t)node * 128 + (lane << 2)) =
            make_float4(ox, oy, oz, ow);
    }
}

// ---------------- host launcher ----------------
extern "C" void kernel_launch(void* const* d_in, const int* in_sizes, int n_in,
                              void* d_out, int out_size)
{
    const float* x     = (const float*)d_in[0];
    const int*   ei    = (const int*)  d_in[1];
    const float* W1l   = (const float*)d_in[2];
    const float* b1l   = (const float*)d_in[3];
    const float* W1r   = (const float*)d_in[4];
    const float* b1r   = (const float*)d_in[5];
    const float* att1  = (const float*)d_in[6];
    const float* bias1 = (const float*)d_in[7];
    const float* W2l   = (const float*)d_in[8];
    const float* b2l   = (const float*)d_in[9];
    const float* W2r   = (const float*)d_in[10];
    const float* b2r   = (const float*)d_in[11];
    const float* att2  = (const float*)d_in[12];
    const float* bias2 = (const float*)d_in[13];

    int N = in_sizes[0] / 128;
    int E = in_sizes[1] / 2;
    int tiles = (N + 127) / 128;
    int sblocks = (N + 1023) / 1024;

    void *p_xl, *p_xr, *p_Ah, *p_counts, *p_pflag;
    cudaGetSymbolAddress(&p_xl, g_xl);
    cudaGetSymbolAddress(&p_xr, g_xr);
    cudaGetSymbolAddress(&p_Ah, g_Ah);
    cudaGetSymbolAddress(&p_counts, g_counts);
    cudaGetSymbolAddress(&p_pflag, g_pflag);
    float* xl = (float*)p_xl;
    float* xr = (float*)p_xr;
    unsigned short* Ahp = (unsigned short*)p_Ah;

    static cudaStream_t s_csr = nullptr;
    static cudaEvent_t ev_fork = nullptr, ev_join = nullptr;
    static bool s_attr = false;
    if (s_csr == nullptr) {
        cudaStreamCreateWithFlags(&s_csr, cudaStreamNonBlocking);
        cudaEventCreateWithFlags(&ev_fork, cudaEventDisableTiming);
        cudaEventCreateWithFlags(&ev_join, cudaEventDisableTiming);
    }
    if (!s_attr) {
        cudaFuncSetAttribute(k_gemm_mma<false>,
                             cudaFuncAttributeMaxDynamicSharedMemorySize, GEMM_SMEM_BYTES);
        cudaFuncSetAttribute(k_gemm_mma<true>,
                             cudaFuncAttributeMaxDynamicSharedMemorySize, GEMM_SMEM_BYTES);
        s_attr = true;
    }

    const int TB = 256;
    int ablocks = (N * 32 + TB - 1) / TB;
    int qblocks = ((E + 3) / 4 + TB - 1) / TB;
    dim3 ggrid(tiles, 2);

    // Fork: CSR build on side stream, overlapped with cvtW + gemm1 on main.
    // gemm1 stays at kernel #4 (ncu capture window) to verify the 2-pass fix.
    cudaEventRecord(ev_fork, 0);
    cudaStreamWaitEvent(s_csr, ev_fork, 0);
    cudaMemsetAsync(p_counts, 0, (size_t)N * sizeof(int), s_csr);
    cudaMemsetAsync(p_pflag, 0, 64 * sizeof(int), s_csr);
    k_cvtW_all<<<256, TB>>>(W1l, W1r, W2l, W2r);              // #1 (main)
    k_hist<<<qblocks, TB, 0, s_csr>>>(ei, E);                 // #2 (side)
    k_scan_one<<<sblocks, 1024, 0, s_csr>>>(N);               // #3 (side)
    k_gemm_mma<false><<<ggrid, TB, GEMM_SMEM_BYTES>>>(x, b1l, xl, b1r, xr, 0, N); // #4 <- ncu
    k_scatter<<<qblocks, TB, 0, s_csr>>>(ei, E);              // #5 (side)
    cudaEventRecord(ev_join, s_csr);

    cudaStreamWaitEvent(0, ev_join, 0);
    k_agg<false, true, true><<<ablocks, TB>>>(xl, xr, att1, bias1,
                                              nullptr, Ahp, N);

    // Layer 2 (A staged from agg1's fp16 output)
    k_gemm_mma<true><<<ggrid, TB, GEMM_SMEM_BYTES>>>(nullptr, b2l, xl, b2r, xr, 2, N);
    k_agg<true, false, false><<<ablocks, TB>>>(xl, xr, att2, bias2,
                                               (float*)d_out, nullptr, N);
}